// round 2
// baseline (speedup 1.0000x reference)
#include <cuda_runtime.h>

#define CCH    64
#define HWDIM  64
#define NPIX   4096
#define CKK1   577                 // Cin*K*K + 1 (bias col)
#define EMB_ROW (CCH * CKK1)       // 36928 floats per bucket
#define NT     216                 // bucket types
#define PXT    16                  // pixels per chunk
#define MAXCH  512                 // >= worst-case total chunks (458)
#define DYN_GRID 464
#define ROWSTR 580                 // 577 padded to mult-of-4 (float4 + banks)
#define PSTR   580
#define SRELSTR 17

// ---- scratch (allocation-free rule: device globals) ----
__device__ float g_h[CCH * NPIX];
__device__ int   g_off[NT + 1];
__device__ int   g_pix[NPIX];
__device__ int   g_chunk_bucket[MAXCH];
__device__ int   g_chunk_base[MAXCH];
__device__ int   g_chunk_cnt[MAXCH];
__device__ int   g_nchunks;

// ---------------------------------------------------------------------------
// body1: grouped 3x3 conv (groups=4) + bias + ReLU. 4-px sliding window per
// thread (halves LDG count). 65536 threads; c uniform within a block.
// ---------------------------------------------------------------------------
__global__ void body1_kernel(const float* __restrict__ x,
                             const float* __restrict__ w1,
                             const float* __restrict__ b1) {
    int t  = blockIdx.x * 256 + threadIdx.x;   // 0..65535
    int c  = t >> 10;                          // out channel (uniform per block)
    int q  = t & 1023;                         // pixel quad within channel
    int y  = q >> 4;
    int x0 = (q & 15) << 2;
    int g  = c >> 4;

    const float* wrow = w1 + c * 144;
    float bb = b1[c];
    float a0 = bb, a1 = bb, a2 = bb, a3 = bb;

    #pragma unroll
    for (int ic = 0; ic < 16; ++ic) {
        const float* xin = x + (g * 16 + ic) * NPIX;
        const float* wk  = wrow + ic * 9;
        #pragma unroll
        for (int ky = 0; ky < 3; ++ky) {
            int yy = y + ky - 1;
            if ((unsigned)yy < (unsigned)HWDIM) {
                const float* rowp = xin + yy * HWDIM;
                float v[6];
                #pragma unroll
                for (int j = 0; j < 6; ++j) {
                    int xx = x0 - 1 + j;
                    v[j] = ((unsigned)xx < (unsigned)HWDIM) ? rowp[xx] : 0.0f;
                }
                #pragma unroll
                for (int kx = 0; kx < 3; ++kx) {
                    float w = wk[ky * 3 + kx];
                    a0 = fmaf(w, v[kx + 0], a0);
                    a1 = fmaf(w, v[kx + 1], a1);
                    a2 = fmaf(w, v[kx + 2], a2);
                    a3 = fmaf(w, v[kx + 3], a3);
                }
            }
        }
    }
    float* dst = g_h + c * NPIX + y * HWDIM + x0;
    dst[0] = fmaxf(a0, 0.0f);
    dst[1] = fmaxf(a1, 0.0f);
    dst[2] = fmaxf(a2, 0.0f);
    dst[3] = fmaxf(a3, 0.0f);
}

// ---------------------------------------------------------------------------
// prep: histogram + scan + chunk list + scatter, in ONE 256-thread CTA.
// ---------------------------------------------------------------------------
__global__ void prep_kernel(const int* __restrict__ buckets) {
    __shared__ int cnt[256], scn[256], offs[256], fil[256], chs[256];
    int tid = threadIdx.x;
    cnt[tid] = 0; fil[tid] = 0;
    __syncthreads();
    for (int p = tid; p < NPIX; p += 256) atomicAdd(&cnt[buckets[p]], 1);
    __syncthreads();

    // inclusive scan of counts
    scn[tid] = cnt[tid];
    __syncthreads();
    for (int d = 1; d < 256; d <<= 1) {
        int v = (tid >= d) ? scn[tid - d] : 0;
        __syncthreads();
        scn[tid] += v;
        __syncthreads();
    }
    int myoff = scn[tid] - cnt[tid];          // exclusive prefix
    offs[tid] = myoff;
    if (tid < NT) g_off[tid] = myoff;
    if (tid == NT - 1) g_off[NT] = scn[tid];

    // scan of chunk counts
    int nch = (tid < NT) ? ((cnt[tid] + PXT - 1) >> 4) : 0;
    chs[tid] = nch;
    __syncthreads();
    for (int d = 1; d < 256; d <<= 1) {
        int v = (tid >= d) ? chs[tid - d] : 0;
        __syncthreads();
        chs[tid] += v;
        __syncthreads();
    }
    int chbase = chs[tid] - nch;
    if (tid < NT) {
        int c = cnt[tid];
        for (int j = 0; j < nch; ++j) {
            g_chunk_bucket[chbase + j] = tid;
            g_chunk_base[chbase + j]   = myoff + j * PXT;
            g_chunk_cnt[chbase + j]    = min(PXT, c - j * PXT);
        }
    }
    if (tid == 255) g_nchunks = chs[255];
    __syncthreads();

    // scatter pixel ids grouped by bucket
    for (int p = tid; p < NPIX; p += 256) {
        int b = buckets[p];
        int pos = offs[b] + atomicAdd(&fil[b], 1);
        g_pix[pos] = p;
    }
}

// ---------------------------------------------------------------------------
// dyn: one CTA per (bucket, <=16-pixel chunk). 128 threads.
//   - patches (577 incl. bias col) for 16 px staged in smem once
//   - filter rows streamed in two 32-row chunks from L2 into smem
//   - 2o x 2px register tile, float4 smem reads (4 B/FMA crossbar)
//   - fused ReLU -> 1x1 conv (w2,b2) -> residual(x) -> ReLU
// ---------------------------------------------------------------------------
__global__ void __launch_bounds__(128)
dyn_kernel(const float* __restrict__ emb,
           const float* __restrict__ w2,
           const float* __restrict__ b2,
           const float* __restrict__ x,
           float*       __restrict__ out) {
    extern __shared__ __align__(16) float smem[];
    float* rows_s  = smem;                       // 32 * 580
    float* patch_s = smem + 32 * ROWSTR;         // 16 * 580
    float* srel    = patch_s + PXT * PSTR;       // 64 * 17
    int*   pixl    = (int*)(srel + CCH * SRELSTR);  // 16 ints

    int bid = blockIdx.x;
    if (bid >= g_nchunks) return;
    int bkt  = g_chunk_bucket[bid];
    int base = g_chunk_base[bid];
    int npx  = g_chunk_cnt[bid];

    int tid  = threadIdx.x;
    int ot   = tid & 15;          // 16 o-threads (x2 rows each)
    int ptid = tid >> 4;          // 8 px-threads (x2 px each: ptid, ptid+8)

    if (tid < PXT) pixl[tid] = (tid < npx) ? g_pix[base + tid] : 0;
    __syncthreads();

    // build patches (order: cin*9 + ky*3 + kx; col 576 = 1.0 bias)
    for (int idx = tid; idx < PXT * CKK1; idx += 128) {
        int px = idx / CKK1;
        int i  = idx - px * CKK1;
        float v = 0.0f;
        if (px < npx) {
            if (i == CKK1 - 1) v = 1.0f;
            else {
                int p = pixl[px];
                int y = p >> 6, xx = p & 63;
                int cin = i / 9;
                int r   = i - cin * 9;
                int ky  = r / 3, kx = r - ky * 3;
                int yy  = y + ky - 1, x2 = xx + kx - 1;
                if ((unsigned)yy < (unsigned)HWDIM && (unsigned)x2 < (unsigned)HWDIM)
                    v = g_h[cin * NPIX + yy * HWDIM + x2];
            }
        }
        patch_s[px * PSTR + i] = v;
    }

    const float* embb = emb + (size_t)bkt * EMB_ROW;

    #pragma unroll 1
    for (int co = 0; co < 2; ++co) {
        __syncthreads();
        // stage 32 contiguous filter rows from L2
        const float* src = embb + co * 32 * CKK1;
        #pragma unroll 4
        for (int idx = tid; idx < 32 * CKK1; idx += 128) {
            int r  = idx / CKK1;
            int cc = idx - r * CKK1;
            rows_s[r * ROWSTR + cc] = src[idx];
        }
        __syncthreads();

        const float4* R0 = (const float4*)(rows_s + ot * ROWSTR);
        const float4* R1 = (const float4*)(rows_s + (ot + 16) * ROWSTR);
        const float4* P0 = (const float4*)(patch_s + ptid * PSTR);
        const float4* P1 = (const float4*)(patch_s + (ptid + 8) * PSTR);

        float a00 = 0.f, a01 = 0.f, a10 = 0.f, a11 = 0.f;
        #pragma unroll 4
        for (int c4 = 0; c4 < 144; ++c4) {       // covers c = 0..575
            float4 r0 = R0[c4], r1 = R1[c4], p0 = P0[c4], p1 = P1[c4];
            a00 = fmaf(r0.x, p0.x, a00); a00 = fmaf(r0.y, p0.y, a00);
            a00 = fmaf(r0.z, p0.z, a00); a00 = fmaf(r0.w, p0.w, a00);
            a01 = fmaf(r0.x, p1.x, a01); a01 = fmaf(r0.y, p1.y, a01);
            a01 = fmaf(r0.z, p1.z, a01); a01 = fmaf(r0.w, p1.w, a01);
            a10 = fmaf(r1.x, p0.x, a10); a10 = fmaf(r1.y, p0.y, a10);
            a10 = fmaf(r1.z, p0.z, a10); a10 = fmaf(r1.w, p0.w, a10);
            a11 = fmaf(r1.x, p1.x, a11); a11 = fmaf(r1.y, p1.y, a11);
            a11 = fmaf(r1.z, p1.z, a11); a11 = fmaf(r1.w, p1.w, a11);
        }
        // bias column (c = 576); patch[.,576] is 1 for valid px, 0 otherwise
        float pb0 = patch_s[ptid * PSTR + 576];
        float pb1 = patch_s[(ptid + 8) * PSTR + 576];
        float rb0 = rows_s[ot * ROWSTR + 576];
        float rb1 = rows_s[(ot + 16) * ROWSTR + 576];
        a00 = fmaf(rb0, pb0, a00);  a01 = fmaf(rb0, pb1, a01);
        a10 = fmaf(rb1, pb0, a10);  a11 = fmaf(rb1, pb1, a11);

        int o0 = co * 32 + ot, o1 = o0 + 16;
        srel[o0 * SRELSTR + ptid]     = fmaxf(a00, 0.0f);
        srel[o0 * SRELSTR + ptid + 8] = fmaxf(a01, 0.0f);
        srel[o1 * SRELSTR + ptid]     = fmaxf(a10, 0.0f);
        srel[o1 * SRELSTR + ptid + 8] = fmaxf(a11, 0.0f);
    }
    __syncthreads();

    // 1x1 conv + bias + residual + final ReLU (8 outputs per thread)
    int oo  = tid >> 1;
    int pxb = (tid & 1) * 8;
    const float* w2row = w2 + oo * CCH;
    float bb = b2[oo];
    float acc[8];
    #pragma unroll
    for (int j = 0; j < 8; ++j) acc[j] = bb;
    #pragma unroll 8
    for (int k = 0; k < CCH; ++k) {
        float w = w2row[k];
        const float* sr = srel + k * SRELSTR + pxb;
        #pragma unroll
        for (int j = 0; j < 8; ++j) acc[j] = fmaf(w, sr[j], acc[j]);
    }
    #pragma unroll
    for (int j = 0; j < 8; ++j) {
        int px = pxb + j;
        if (px < npx) {
            int p  = pixl[px];
            int oi = oo * NPIX + p;
            out[oi] = fmaxf(acc[j] + x[oi], 0.0f);
        }
    }
}

// ---------------------------------------------------------------------------
extern "C" void kernel_launch(void* const* d_in, const int* in_sizes, int n_in,
                              void* d_out, int out_size) {
    const float* x       = (const float*)d_in[0];
    const int*   buckets = (const int*)  d_in[1];
    const float* w1      = (const float*)d_in[2];
    const float* b1      = (const float*)d_in[3];
    const float* emb     = (const float*)d_in[4];
    const float* w2      = (const float*)d_in[5];
    const float* b2      = (const float*)d_in[6];
    float*       out     = (float*)d_out;

    const int smem_bytes = (32 * ROWSTR + PXT * PSTR + CCH * SRELSTR) * 4
                           + PXT * 4;   // 115,776 B
    // capture-safe (not a stream op); needed for >48KB dynamic smem
    cudaFuncSetAttribute(dyn_kernel,
                         cudaFuncAttributeMaxDynamicSharedMemorySize, smem_bytes);

    body1_kernel<<<256, 256>>>(x, w1, b1);
    prep_kernel<<<1, 256>>>(buckets);
    dyn_kernel<<<DYN_GRID, 128, smem_bytes>>>(emb, w2, b2, x, out);
}

// round 3
// speedup vs baseline: 1.9493x; 1.9493x over previous
#include <cuda_runtime.h>

#define CCH    64
#define HWDIM  64
#define NPIX   4096
#define CKK1   577                 // Cin*K*K + 1 (bias col)
#define EMB_ROW (CCH * CKK1)       // 36928 floats per bucket
#define NT     216
#define PXT    32                  // pixels per chunk
#define MAXCH  352                 // >= worst-case sum ceil(cnt/32) = 337
#define ROWSTR 580                 // conflict-free for 8-distinct-row warp loads
#define PSTR   580
#define SSTR   36                  // srel stride (16B-aligned float4 rows)
#define WTSTR  65                  // transposed-w2 stride

// ---- scratch (allocation-free rule: device globals) ----
__device__ float g_h[CCH * NPIX];
__device__ int   g_pix[NPIX];
__device__ int   g_chunk_bucket[MAXCH];
__device__ int   g_chunk_base[MAXCH];
__device__ int   g_chunk_cnt[MAXCH];
__device__ int   g_nchunks;

// ---------------------------------------------------------------------------
// body1: grouped 3x3 conv (groups=4) + bias + ReLU. 2 px/thread, 131072
// threads (512 blocks) for occupancy; c uniform within a block.
// ---------------------------------------------------------------------------
__global__ void __launch_bounds__(256)
body1_kernel(const float* __restrict__ x,
             const float* __restrict__ w1,
             const float* __restrict__ b1) {
    int t  = blockIdx.x * 256 + threadIdx.x;   // 0..131071
    int c  = t >> 11;                          // out channel
    int q  = t & 2047;
    int y  = q >> 5;
    int x0 = (q & 31) << 1;
    int g  = c >> 4;

    const float* wrow = w1 + c * 144;
    float bb = b1[c];
    float a0 = bb, a1 = bb;

    #pragma unroll 4
    for (int ic = 0; ic < 16; ++ic) {
        const float* xin = x + (g * 16 + ic) * NPIX;
        const float* wk  = wrow + ic * 9;
        #pragma unroll
        for (int ky = 0; ky < 3; ++ky) {
            int yy = y + ky - 1;
            if ((unsigned)yy < (unsigned)HWDIM) {
                const float* rowp = xin + yy * HWDIM;
                float v[4];
                #pragma unroll
                for (int j = 0; j < 4; ++j) {
                    int xx = x0 - 1 + j;
                    v[j] = ((unsigned)xx < (unsigned)HWDIM) ? __ldg(rowp + xx) : 0.0f;
                }
                #pragma unroll
                for (int kx = 0; kx < 3; ++kx) {
                    float w = wk[ky * 3 + kx];
                    a0 = fmaf(w, v[kx],     a0);
                    a1 = fmaf(w, v[kx + 1], a1);
                }
            }
        }
    }
    float* dst = g_h + c * NPIX + y * HWDIM + x0;
    dst[0] = fmaxf(a0, 0.0f);
    dst[1] = fmaxf(a1, 0.0f);
}

// ---------------------------------------------------------------------------
// prep: histogram + scan + chunk list + scatter, one 256-thread CTA.
// ---------------------------------------------------------------------------
__global__ void prep_kernel(const int* __restrict__ buckets) {
    __shared__ int cnt[256], scn[256], offs[256], fil[256], chs[256];
    int tid = threadIdx.x;
    cnt[tid] = 0; fil[tid] = 0;
    __syncthreads();
    for (int p = tid; p < NPIX; p += 256) atomicAdd(&cnt[buckets[p]], 1);
    __syncthreads();

    scn[tid] = cnt[tid];
    __syncthreads();
    for (int d = 1; d < 256; d <<= 1) {
        int v = (tid >= d) ? scn[tid - d] : 0;
        __syncthreads();
        scn[tid] += v;
        __syncthreads();
    }
    int myoff = scn[tid] - cnt[tid];
    offs[tid] = myoff;

    int nch = (tid < NT) ? ((cnt[tid] + PXT - 1) >> 5) : 0;
    chs[tid] = nch;
    __syncthreads();
    for (int d = 1; d < 256; d <<= 1) {
        int v = (tid >= d) ? chs[tid - d] : 0;
        __syncthreads();
        chs[tid] += v;
        __syncthreads();
    }
    int chbase = chs[tid] - nch;
    if (tid < NT) {
        int c = cnt[tid];
        for (int j = 0; j < nch; ++j) {
            g_chunk_bucket[chbase + j] = tid;
            g_chunk_base[chbase + j]   = myoff + j * PXT;
            g_chunk_cnt[chbase + j]    = min(PXT, c - j * PXT);
        }
    }
    if (tid == 255) g_nchunks = chs[255];
    __syncthreads();

    for (int p = tid; p < NPIX; p += 256) {
        int b = buckets[p];
        int pos = offs[b] + atomicAdd(&fil[b], 1);
        g_pix[pos] = p;
    }
}

// ---------------------------------------------------------------------------
// dyn: one CTA per (bucket, <=32-pixel chunk). 128 threads.
//   - all 64 filter rows resident in smem (float4-staged from L2)
//   - 32 patches (577 incl. bias) in smem
//   - 8-row x 2-px register tile (16 acc), conflict-free LDS
//   - fused ReLU -> 1x1 conv (w2 staged transposed in smem) -> +x -> ReLU
// smem: rows 64*580 | patch 32*580 (later overlaid by srel 64*36) | pixl
// ---------------------------------------------------------------------------
__global__ void __launch_bounds__(128)
dyn_kernel(const float* __restrict__ emb,
           const float* __restrict__ w2,
           const float* __restrict__ b2,
           const float* __restrict__ x,
           float*       __restrict__ out) {
    extern __shared__ __align__(16) float smem[];
    float* rows_s  = smem;                        // 64*580 floats
    float* patch_s = smem + 64 * ROWSTR;          // 32*580 floats
    float* srel    = patch_s;                     // overlay (after compute)
    float* wT      = rows_s;                      // overlay (after compute)
    int*   pixl    = (int*)(patch_s + PXT * PSTR);

    int bid = blockIdx.x;
    if (bid >= g_nchunks) return;
    int bkt  = g_chunk_bucket[bid];
    int base = g_chunk_base[bid];
    int npx  = g_chunk_cnt[bid];

    int tid = threadIdx.x;
    int ot  = tid & 7;            // 8 row-slots: rows ot+8k, k=0..7
    int pt  = tid >> 3;           // 16 px-slots: px pt, pt+16

    if (tid < PXT) pixl[tid] = (tid < npx) ? g_pix[base + tid] : 0;
    __syncthreads();

    // --- stage all 64 filter rows: coalesced float4 LDG, scalar scatter ---
    const float*  embb  = emb + (size_t)bkt * EMB_ROW;
    const float4* embb4 = (const float4*)embb;          // 16B aligned
    #pragma unroll 4
    for (int i4 = tid; i4 < EMB_ROW / 4; i4 += 128) {   // 9232 float4s
        float4 v = __ldg(embb4 + i4);
        int e = i4 << 2;
        int r0 = e / CKK1;          int c0 = e - r0 * CKK1;
        rows_s[r0 * ROWSTR + c0] = v.x;
        e++; r0 = e / CKK1; c0 = e - r0 * CKK1;
        rows_s[r0 * ROWSTR + c0] = v.y;
        e++; r0 = e / CKK1; c0 = e - r0 * CKK1;
        rows_s[r0 * ROWSTR + c0] = v.z;
        e++; r0 = e / CKK1; c0 = e - r0 * CKK1;
        rows_s[r0 * ROWSTR + c0] = v.w;
    }

    // --- build patches (order cin*9 + ky*3 + kx; col 576 = 1.0 bias) ---
    for (int idx = tid; idx < PXT * CKK1; idx += 128) {
        int px = idx / CKK1;
        int i  = idx - px * CKK1;
        float v = 0.0f;
        if (px < npx) {
            if (i == CKK1 - 1) v = 1.0f;
            else {
                int p  = pixl[px];
                int y  = p >> 6, xx = p & 63;
                int cin = i / 9;
                int r   = i - cin * 9;
                int ky  = r / 3, kx = r - ky * 3;
                int yy  = y + ky - 1, x2 = xx + kx - 1;
                if ((unsigned)yy < (unsigned)HWDIM && (unsigned)x2 < (unsigned)HWDIM)
                    v = g_h[cin * NPIX + yy * HWDIM + x2];
            }
        }
        patch_s[px * PSTR + i] = v;
    }
    __syncthreads();

    // --- dynamic conv: 8 rows x 2 px per thread ---
    float acc[8][2];
    #pragma unroll
    for (int k = 0; k < 8; ++k) { acc[k][0] = 0.f; acc[k][1] = 0.f; }

    const float4* p0 = (const float4*)(patch_s + pt * PSTR);
    const float4* p1 = (const float4*)(patch_s + (pt + 16) * PSTR);

    #pragma unroll 2
    for (int c4 = 0; c4 < 144; ++c4) {           // cols 0..575
        float4 pa = p0[c4];
        float4 pb = p1[c4];
        #pragma unroll
        for (int k = 0; k < 8; ++k) {
            float4 r = *(const float4*)(rows_s + (ot + 8 * k) * ROWSTR + (c4 << 2));
            float a = acc[k][0], b = acc[k][1];
            a = fmaf(r.x, pa.x, a); b = fmaf(r.x, pb.x, b);
            a = fmaf(r.y, pa.y, a); b = fmaf(r.y, pb.y, b);
            a = fmaf(r.z, pa.z, a); b = fmaf(r.z, pb.z, b);
            a = fmaf(r.w, pa.w, a); b = fmaf(r.w, pb.w, b);
            acc[k][0] = a; acc[k][1] = b;
        }
    }
    // bias column (576): patch bias is 1 for valid px, 0 otherwise
    float pba = patch_s[pt * PSTR + 576];
    float pbb = patch_s[(pt + 16) * PSTR + 576];
    #pragma unroll
    for (int k = 0; k < 8; ++k) {
        float rb = rows_s[(ot + 8 * k) * ROWSTR + 576];
        acc[k][0] = fmaf(rb, pba, acc[k][0]);
        acc[k][1] = fmaf(rb, pbb, acc[k][1]);
    }

    __syncthreads();   // all reads of rows_s / patch_s done before overlays

    // srel (ReLU of dyn output) overlays patch region; wT overlays rows region
    #pragma unroll
    for (int k = 0; k < 8; ++k) {
        srel[(ot + 8 * k) * SSTR + pt]      = fmaxf(acc[k][0], 0.0f);
        srel[(ot + 8 * k) * SSTR + pt + 16] = fmaxf(acc[k][1], 0.0f);
    }
    // stage w2 transposed: wT[k*WTSTR + oc] = w2[oc*64 + k]
    for (int i = tid; i < CCH * CCH; i += 128) {
        int oc = i >> 6, k = i & 63;
        wT[k * WTSTR + oc] = __ldg(w2 + i);
    }
    __syncthreads();

    // --- 1x1 conv + bias + residual + final ReLU ---
    // thread: oc pair {ocg, ocg+32}, px group pxg*8 .. pxg*8+7
    int ocg = tid & 31;
    int pxg = tid >> 5;
    float accA[8], accB[8];
    float bA = b2[ocg], bB = b2[ocg + 32];
    #pragma unroll
    for (int j = 0; j < 8; ++j) { accA[j] = bA; accB[j] = bB; }

    const float4* srl = (const float4*)(srel + pxg * 8);
    #pragma unroll 4
    for (int k = 0; k < CCH; ++k) {
        float wa = wT[k * WTSTR + ocg];
        float wb = wT[k * WTSTR + ocg + 32];
        float4 s0 = srl[k * (SSTR / 4)];
        float4 s1 = srl[k * (SSTR / 4) + 1];
        accA[0] = fmaf(wa, s0.x, accA[0]); accB[0] = fmaf(wb, s0.x, accB[0]);
        accA[1] = fmaf(wa, s0.y, accA[1]); accB[1] = fmaf(wb, s0.y, accB[1]);
        accA[2] = fmaf(wa, s0.z, accA[2]); accB[2] = fmaf(wb, s0.z, accB[2]);
        accA[3] = fmaf(wa, s0.w, accA[3]); accB[3] = fmaf(wb, s0.w, accB[3]);
        accA[4] = fmaf(wa, s1.x, accA[4]); accB[4] = fmaf(wb, s1.x, accB[4]);
        accA[5] = fmaf(wa, s1.y, accA[5]); accB[5] = fmaf(wb, s1.y, accB[5]);
        accA[6] = fmaf(wa, s1.z, accA[6]); accB[6] = fmaf(wb, s1.z, accB[6]);
        accA[7] = fmaf(wa, s1.w, accA[7]); accB[7] = fmaf(wb, s1.w, accB[7]);
    }
    #pragma unroll
    for (int j = 0; j < 8; ++j) {
        int px = pxg * 8 + j;
        if (px < npx) {
            int p   = pixl[px];
            int oiA = ocg * NPIX + p;
            int oiB = (ocg + 32) * NPIX + p;
            out[oiA] = fmaxf(accA[j] + x[oiA], 0.0f);
            out[oiB] = fmaxf(accB[j] + x[oiB], 0.0f);
        }
    }
}

// ---------------------------------------------------------------------------
extern "C" void kernel_launch(void* const* d_in, const int* in_sizes, int n_in,
                              void* d_out, int out_size) {
    const float* x       = (const float*)d_in[0];
    const int*   buckets = (const int*)  d_in[1];
    const float* w1      = (const float*)d_in[2];
    const float* b1      = (const float*)d_in[3];
    const float* emb     = (const float*)d_in[4];
    const float* w2      = (const float*)d_in[5];
    const float* b2      = (const float*)d_in[6];
    float*       out     = (float*)d_out;

    const int smem_bytes = (64 * ROWSTR + PXT * PSTR) * 4 + PXT * 4; // 224,384 B
    cudaFuncSetAttribute(dyn_kernel,
                         cudaFuncAttributeMaxDynamicSharedMemorySize, smem_bytes);

    body1_kernel<<<512, 256>>>(x, w1, b1);
    prep_kernel<<<1, 256>>>(buckets);
    dyn_kernel<<<MAXCH, 128, smem_bytes>>>(emb, w2, b2, x, out);
}